// round 14
// baseline (speedup 1.0000x reference)
#include <cuda_runtime.h>
#include <cuda_bf16.h>
#include <mma.h>
#include <cstdint>
#include <cstddef>

using namespace nvcuda;

#define T_SEQ 1024
#define B_SZ  64
// E = 256, H = 256, 4H = 1024

// ---------------- device-global scratch (no allocations) ----------------
__device__ float g_x   [(size_t)B_SZ * T_SEQ * 256];   // gathered embeddings
__device__ float g_xw1f[(size_t)B_SZ * T_SEQ * 1024];  // x @ fw1_Wi
__device__ float g_xw1b[(size_t)B_SZ * T_SEQ * 1024];  // x @ bw1_Wi
__device__ float g_xw2 [(size_t)B_SZ * T_SEQ * 1024];  // x1 @ fw2_Wi
__device__ float g_x1  [(size_t)B_SZ * T_SEQ * 512];   // layer-1 output [fwd|bwd]
__device__ float g_h2f [B_SZ * 256];                   // layer-2 fwd final h
// padded h buffers: [3 sets][2 parity][8 bg][16 rows][256]; rows 8..15 stay 0
// (static zero-init, never written) so wmma a-fragments read M=16 directly.
#define HBP_SET (2 * 8 * 16 * 256)
__device__ __nv_bfloat16 g_hbp[3 * HBP_SET];
__device__ unsigned g_flags[24 * 32];                  // per-group 16 flags (128B apart)

// ---------------- helpers ----------------
__device__ __forceinline__ float tanh_ap(float x) {
    float y;
    asm("tanh.approx.f32 %0, %1;" : "=f"(y) : "f"(x));
    return y;
}
__device__ __forceinline__ float sig_ap(float x) {
    return fmaf(tanh_ap(0.5f * x), 0.5f, 0.5f);
}
__device__ __forceinline__ float sigf(float x) {
    return __fdividef(1.0f, 1.0f + __expf(-x));
}

// ---------------- init: zero release flags (every replay) ----------------
__global__ void init_kernel() {
    int i = blockIdx.x * blockDim.x + threadIdx.x;
    if (i < 24 * 32) g_flags[i] = 0u;
}

// ---------------- embedding gather ----------------
__global__ void gather_kernel(const int* __restrict__ tok, const float* __restrict__ emb) {
    size_t idx = (size_t)blockIdx.x * blockDim.x + threadIdx.x;  // 65536*64 float4
    int row = (int)(idx >> 6);
    int f   = (int)(idx & 63);
    int t   = __ldg(&tok[row]);
    ((float4*)g_x)[idx] = __ldg(&((const float4*)emb)[(size_t)t * 64 + f]);
}

// ---------------- bf16 WMMA GEMM, double-buffered: C[M,N] = A[M,K] @ B[K,N] ----------------
#define GLDA 40
#define GLDB 136
__global__ __launch_bounds__(256, 2) void gemm_bf16(const float* __restrict__ A,
                                                    const float* __restrict__ B,
                                                    float* __restrict__ C,
                                                    int N, int K) {
    __shared__ __nv_bfloat16 As[2][128 * GLDA];
    __shared__ __nv_bfloat16 Bs[2][32 * GLDB];
    const int tid = threadIdx.x;
    const int w   = tid >> 5;
    const int m0  = blockIdx.y * 128;
    const int n0  = blockIdx.x * 128;
    const int wm0 = (w >> 2) * 64;
    const int wn0 = (w & 3) * 32;

    wmma::fragment<wmma::accumulator, 16, 16, 16, float> c[4][2];
    #pragma unroll
    for (int i = 0; i < 4; i++)
        #pragma unroll
        for (int j = 0; j < 2; j++) wmma::fill_fragment(c[i][j], 0.0f);

    float4 ra[4], rb[4];

    #pragma unroll
    for (int p = 0; p < 4; p++) {
        int idx = tid + p * 256;
        int row = idx >> 3, c4 = idx & 7;
        ra[p] = __ldg(&((const float4*)(A + (size_t)(m0 + row) * K))[c4]);
    }
    #pragma unroll
    for (int p = 0; p < 4; p++) {
        int idx = tid + p * 256;
        int row = idx >> 5, c4 = idx & 31;
        rb[p] = __ldg(&((const float4*)(B + (size_t)row * N + n0))[c4]);
    }
    #pragma unroll
    for (int p = 0; p < 4; p++) {
        int idx = tid + p * 256;
        int row = idx >> 3, c4 = idx & 7;
        __nv_bfloat162* dst = (__nv_bfloat162*)(&As[0][row * GLDA + c4 * 4]);
        dst[0] = __floats2bfloat162_rn(ra[p].x, ra[p].y);
        dst[1] = __floats2bfloat162_rn(ra[p].z, ra[p].w);
    }
    #pragma unroll
    for (int p = 0; p < 4; p++) {
        int idx = tid + p * 256;
        int row = idx >> 5, c4 = idx & 31;
        __nv_bfloat162* dst = (__nv_bfloat162*)(&Bs[0][row * GLDB + c4 * 4]);
        dst[0] = __floats2bfloat162_rn(rb[p].x, rb[p].y);
        dst[1] = __floats2bfloat162_rn(rb[p].z, rb[p].w);
    }
    __syncthreads();

    const int nkt = K >> 5;
    for (int kt = 0; kt < nkt; kt++) {
        const int cur = kt & 1;
        const bool more = (kt + 1 < nkt);
        if (more) {
            #pragma unroll
            for (int p = 0; p < 4; p++) {
                int idx = tid + p * 256;
                int row = idx >> 3, c4 = idx & 7;
                ra[p] = __ldg(&((const float4*)(A + (size_t)(m0 + row) * K + (kt + 1) * 32))[c4]);
            }
            #pragma unroll
            for (int p = 0; p < 4; p++) {
                int idx = tid + p * 256;
                int row = idx >> 5, c4 = idx & 31;
                rb[p] = __ldg(&((const float4*)(B + (size_t)((kt + 1) * 32 + row) * N + n0))[c4]);
            }
        }
        #pragma unroll
        for (int kk = 0; kk < 32; kk += 16) {
            wmma::fragment<wmma::matrix_a, 16, 16, 16, __nv_bfloat16, wmma::row_major> a[4];
            wmma::fragment<wmma::matrix_b, 16, 16, 16, __nv_bfloat16, wmma::row_major> b[2];
            #pragma unroll
            for (int i = 0; i < 4; i++)
                wmma::load_matrix_sync(a[i], &As[cur][(wm0 + i * 16) * GLDA + kk], GLDA);
            #pragma unroll
            for (int j = 0; j < 2; j++)
                wmma::load_matrix_sync(b[j], &Bs[cur][kk * GLDB + wn0 + j * 16], GLDB);
            #pragma unroll
            for (int i = 0; i < 4; i++)
                #pragma unroll
                for (int j = 0; j < 2; j++)
                    wmma::mma_sync(c[i][j], a[i], b[j], c[i][j]);
        }
        if (more) {
            const int nxt = cur ^ 1;
            #pragma unroll
            for (int p = 0; p < 4; p++) {
                int idx = tid + p * 256;
                int row = idx >> 3, c4 = idx & 7;
                __nv_bfloat162* dst = (__nv_bfloat162*)(&As[nxt][row * GLDA + c4 * 4]);
                dst[0] = __floats2bfloat162_rn(ra[p].x, ra[p].y);
                dst[1] = __floats2bfloat162_rn(ra[p].z, ra[p].w);
            }
            #pragma unroll
            for (int p = 0; p < 4; p++) {
                int idx = tid + p * 256;
                int row = idx >> 5, c4 = idx & 31;
                __nv_bfloat162* dst = (__nv_bfloat162*)(&Bs[nxt][row * GLDB + c4 * 4]);
                dst[0] = __floats2bfloat162_rn(rb[p].x, rb[p].y);
                dst[1] = __floats2bfloat162_rn(rb[p].z, rb[p].w);
            }
        }
        __syncthreads();
    }
    #pragma unroll
    for (int i = 0; i < 4; i++)
        #pragma unroll
        for (int j = 0; j < 2; j++)
            wmma::store_matrix_sync(C + (size_t)(m0 + wm0 + i * 16) * N + n0 + wn0 + j * 16,
                                    c[i][j], N, wmma::mem_row_major);
}

// ---------------- persistent LSTM scan: flag sync + direct-global MMA ----------------
// Grid: nDir*128 CTAs, 256 threads. CTA (dir, bg, ng): batch rows bg*8..+8,
// h-cols ng*16..+16 (=> 64 local z-cols). Wh slice in SMEM. h lives in a padded
// global buffer [2][8 bg][16][256] (rows 8..15 = 0); MMA a-fragments load from it
// DIRECTLY (no smem staging, no pre-MMA syncthreads — each warp acquires via its
// own flag poll). Sync: 16 per-CTA flag words per group, st.release / poll-acquire.
#define WHS_LD 72
#define ZB_LD  68
#define WHS_BYTES (256 * WHS_LD * 2)          // 36864
#define ZB_OFF    WHS_BYTES
#define ZB_BYTES  (2 * 16 * ZB_LD * 4)        // 8704 (two K-half planes)
#define SCAN_SMEM (ZB_OFF + ZB_BYTES)         // 45568

__global__ __launch_bounds__(256, 2) void scan_kernel(
    const float* __restrict__ xw_f, const float* __restrict__ xw_b,
    const float* __restrict__ Wh_f, const float* __restrict__ Wh_b,
    const float* __restrict__ b_f,  const float* __restrict__ b_b,
    __nv_bfloat16* hb_base, unsigned* flags_base,
    float* x1out, float* h2out) {
    extern __shared__ char sm[];
    __nv_bfloat16* Whs = (__nv_bfloat16*)sm;
    float*         zb  = (float*)(sm + ZB_OFF);

    const int tid = threadIdx.x;
    const int w   = tid >> 5;
    const int lane = tid & 31;
    const int dir = blockIdx.x >> 7;              // scan2 grid=128 -> always 0
    const int sub = blockIdx.x & 127;
    const int bg  = sub >> 4, ng = sub & 15;
    const int r0  = bg * 8, hc0 = ng * 16;

    const float* xw   = dir ? xw_b : xw_f;
    const float* Whg  = dir ? Wh_b : Wh_f;
    const float* bias = dir ? b_b  : b_f;
    __nv_bfloat16* hbp = hb_base + (size_t)dir * HBP_SET;    // [2][8][16][256]
    unsigned* flagg = flags_base + (dir * 8 + bg) * 32;      // 16 flags, 128B region

    // stage Wh slice bf16: Whs[k][c], c = gate*16+j -> global col gate*256+hc0+j
    for (int i = tid; i < 256 * 64; i += 256) {
        int k = i >> 6, cc = i & 63;
        int gt = cc >> 4, j = cc & 15;
        Whs[k * WHS_LD + cc] =
            __float2bfloat16_rn(__ldg(&Whg[(size_t)k * 1024 + gt * 256 + hc0 + j]));
    }

    // MMA role: K-half q, local col base n0
    const int q  = w >> 2;
    const int n0 = (w & 3) * 16;
    // gate role (tid < 128): row gr, h-col gj
    const int gr = tid >> 4, gj = tid & 15;
    const int xwbase = hc0 + gj;
    float bi = 0.f, bfv = 0.f, bgv = 0.f, bo = 0.f;
    if (tid < 128) {
        bi  = __ldg(&bias[0 * 256 + xwbase]);
        bfv = __ldg(&bias[1 * 256 + xwbase]);
        bgv = __ldg(&bias[2 * 256 + xwbase]);
        bo  = __ldg(&bias[3 * 256 + xwbase]);
    }
    float c_state = 0.0f;
    const float* xwrow = xw + (size_t)(r0 + gr) * T_SEQ * 1024 + xwbase;
    __syncthreads();

    // prefetch xw for steps 0 and 1 (2-deep register pipeline)
    float4 xv0 = make_float4(0.f, 0.f, 0.f, 0.f);
    float4 xv1 = make_float4(0.f, 0.f, 0.f, 0.f);
    if (tid < 128) {
        int ta = dir ? (T_SEQ - 1) : 0;
        int tb = dir ? (T_SEQ - 2) : 1;
        const float* pa = xwrow + (size_t)ta * 1024;
        const float* pb = xwrow + (size_t)tb * 1024;
        xv0.x = __ldcs(pa); xv0.y = __ldcs(pa + 256); xv0.z = __ldcs(pa + 512); xv0.w = __ldcs(pa + 768);
        xv1.x = __ldcs(pb); xv1.y = __ldcs(pb + 256); xv1.z = __ldcs(pb + 512); xv1.w = __ldcs(pb + 768);
    }

    // one scan step; consumes xc (xw for step s), refills it with step s+2
    auto do_step = [&](int s, float4& xc) -> bool {
        if (s > 0) {
            // every warp independently waits for all 16 group flags >= s (acquire)
            {
                const unsigned tgt = (unsigned)s;
                unsigned v = tgt;
                do {
                    if (lane < 16)
                        asm volatile("ld.acquire.gpu.global.u32 %0, [%1];"
                                     : "=r"(v) : "l"(flagg + lane) : "memory");
                } while (__any_sync(0xffffffffu, v < tgt));
            }
            // K-split MMA: a-fragments DIRECT from global padded h (parity s&1)
            {
                const __nv_bfloat16* abase = hbp + (size_t)(s & 1) * (8 * 16 * 256)
                                           + (size_t)bg * (16 * 256);
                wmma::fragment<wmma::accumulator, 16, 16, 16, float> acc;
                wmma::fill_fragment(acc, 0.0f);
                const int kbase = q * 128;
                #pragma unroll
                for (int kt = 0; kt < 8; kt++) {
                    wmma::fragment<wmma::matrix_a, 16, 16, 16, __nv_bfloat16, wmma::row_major> a;
                    wmma::fragment<wmma::matrix_b, 16, 16, 16, __nv_bfloat16, wmma::row_major> b;
                    const int kk = kbase + kt * 16;
                    wmma::load_matrix_sync(a, abase + kk, 256);
                    wmma::load_matrix_sync(b, Whs + kk * WHS_LD + n0, WHS_LD);
                    wmma::mma_sync(acc, a, b, acc);
                }
                wmma::store_matrix_sync(zb + q * (16 * ZB_LD) + n0, acc, ZB_LD, wmma::mem_row_major);
            }
        }
        __syncthreads();

        const bool last = (s == T_SEQ - 1);
        float hval = 0.f;
        if (tid < 128) {
            float zi = bi + xc.x, zf = bfv + xc.y, zg = bgv + xc.z, zo = bo + xc.w;
            if (s > 0) {
                const float* z0 = zb + gr * ZB_LD;
                const float* z1 = z0 + 16 * ZB_LD;
                zi += z0[gj]      + z1[gj];
                zf += z0[16 + gj] + z1[16 + gj];
                zg += z0[32 + gj] + z1[32 + gj];
                zo += z0[48 + gj] + z1[48 + gj];
            }
            c_state = sig_ap(zf) * c_state + sig_ap(zi) * tanh_ap(zg);
            hval = sig_ap(zo) * tanh_ap(c_state);
            if (!last) {
                // publish h(s+1) into padded buffer (parity (s+1)&1)
                __nv_bfloat16 hv = __float2bfloat16_rn(hval);
                __stcg(hbp + (size_t)((s + 1) & 1) * (8 * 16 * 256)
                           + (size_t)bg * (16 * 256) + gr * 256 + hc0 + gj, hv);
            }
        }
        const int t_in = dir ? (T_SEQ - 1 - s) : s;
        if (last) {
            if (tid < 128) {
                if (x1out)
                    __stcg(x1out + ((size_t)(r0 + gr) * T_SEQ + t_in) * 512 + dir * 256 + hc0 + gj, hval);
                if (h2out)
                    h2out[(r0 + gr) * 256 + hc0 + gj] = hval;
            }
            return true;
        }
        __syncthreads();   // all h stores issued before the release store
        if (tid == 0)
            asm volatile("st.release.gpu.global.u32 [%0], %1;"
                         :: "l"(flagg + ng), "r"((unsigned)(s + 1)) : "memory");
        // post-release: bulk output store + 2-ahead prefetch (off the release path)
        if (tid < 128) {
            if (x1out)
                __stcg(x1out + ((size_t)(r0 + gr) * T_SEQ + t_in) * 512 + dir * 256 + hc0 + gj, hval);
            if (s + 2 < T_SEQ) {
                int tn = dir ? (T_SEQ - 1 - (s + 2)) : (s + 2);
                const float* p = xwrow + (size_t)tn * 1024;
                xc.x = __ldcs(p); xc.y = __ldcs(p + 256); xc.z = __ldcs(p + 512); xc.w = __ldcs(p + 768);
            }
        }
        return false;
    };

    for (int s = 0; s < T_SEQ; s += 2) {
        if (do_step(s, xv0)) break;
        if (do_step(s + 1, xv1)) break;
    }
}

// ---------------- head: layer-2 bwd single step + final dot + sigmoid ----------------
__global__ __launch_bounds__(256) void head_kernel(const float* __restrict__ Wi,
                                                   const float* __restrict__ b2,
                                                   const float* __restrict__ Wd,
                                                   const float* __restrict__ bd,
                                                   float* __restrict__ out) {
    __shared__ float xr[512];
    __shared__ float z[1024];
    __shared__ float red[8];
    const int b = blockIdx.x, tid = threadIdx.x;
    const float* xrow = g_x1 + ((size_t)b * T_SEQ + (T_SEQ - 1)) * 512;
    xr[tid] = xrow[tid];
    xr[tid + 256] = xrow[tid + 256];
    __syncthreads();
    const int c0 = tid * 4;
    float4 acc = *(const float4*)(b2 + c0);
    for (int k = 0; k < 512; k++) {
        float xv = xr[k];
        float4 wv = __ldg((const float4*)(Wi + (size_t)k * 1024 + c0));
        acc.x = fmaf(xv, wv.x, acc.x);
        acc.y = fmaf(xv, wv.y, acc.y);
        acc.z = fmaf(xv, wv.z, acc.z);
        acc.w = fmaf(xv, wv.w, acc.w);
    }
    *(float4*)(z + c0) = acc;
    __syncthreads();
    float zi = z[tid], zg = z[512 + tid], zo = z[768 + tid];
    float cst = sigf(zi) * tanhf(zg);           // c0 = 0 so forget term vanishes
    float h2b = sigf(zo) * tanhf(cst);
    float pl = g_h2f[b * 256 + tid] * __ldg(&Wd[tid]) + h2b * __ldg(&Wd[256 + tid]);
    #pragma unroll
    for (int off = 16; off; off >>= 1) pl += __shfl_down_sync(0xffffffffu, pl, off);
    if ((tid & 31) == 0) red[tid >> 5] = pl;
    __syncthreads();
    if (tid == 0) {
        float ssum = 0.f;
        #pragma unroll
        for (int q = 0; q < 8; q++) ssum += red[q];
        out[b] = sigf(ssum + bd[0]);
    }
}

// ---------------- launch ----------------
extern "C" void kernel_launch(void* const* d_in, const int* in_sizes, int n_in,
                              void* d_out, int out_size) {
    const int*   tokens = (const int*)  d_in[0];
    const float* embed  = (const float*)d_in[1];
    const float* fw1_Wi = (const float*)d_in[2];
    const float* fw1_Wh = (const float*)d_in[3];
    const float* fw1_b  = (const float*)d_in[4];
    const float* bw1_Wi = (const float*)d_in[5];
    const float* bw1_Wh = (const float*)d_in[6];
    const float* bw1_b  = (const float*)d_in[7];
    const float* fw2_Wi = (const float*)d_in[8];
    const float* fw2_Wh = (const float*)d_in[9];
    const float* fw2_b  = (const float*)d_in[10];
    const float* bw2_Wi = (const float*)d_in[11];
    const float* bw2_b  = (const float*)d_in[13];
    const float* Wd     = (const float*)d_in[14];
    const float* bd     = (const float*)d_in[15];
    float* out = (float*)d_out;

    float *px, *pxw1f, *pxw1b, *pxw2, *px1, *ph2f;
    __nv_bfloat16* phbp;
    unsigned* pflags;
    cudaGetSymbolAddress((void**)&px,    g_x);
    cudaGetSymbolAddress((void**)&pxw1f, g_xw1f);
    cudaGetSymbolAddress((void**)&pxw1b, g_xw1b);
    cudaGetSymbolAddress((void**)&pxw2,  g_xw2);
    cudaGetSymbolAddress((void**)&px1,   g_x1);
    cudaGetSymbolAddress((void**)&ph2f,  g_h2f);
    cudaGetSymbolAddress((void**)&phbp,  g_hbp);
    cudaGetSymbolAddress((void**)&pflags, g_flags);

    cudaFuncSetAttribute(scan_kernel, cudaFuncAttributeMaxDynamicSharedMemorySize, SCAN_SMEM);

    init_kernel<<<3, 256>>>();
    gather_kernel<<<16384, 256>>>(tokens, embed);
    gemm_bf16<<<dim3(8, 512), 256>>>(px, fw1_Wi, pxw1f, 1024, 256);
    gemm_bf16<<<dim3(8, 512), 256>>>(px, bw1_Wi, pxw1b, 1024, 256);
    scan_kernel<<<256, 256, SCAN_SMEM>>>(pxw1f, pxw1b, fw1_Wh, bw1_Wh, fw1_b, bw1_b,
                                         phbp, pflags, px1, nullptr);
    gemm_bf16<<<dim3(8, 512), 256>>>(px1, fw2_Wi, pxw2, 1024, 512);
    scan_kernel<<<128, 256, SCAN_SMEM>>>(pxw2, pxw2, fw2_Wh, fw2_Wh, fw2_b, fw2_b,
                                         phbp + (size_t)2 * HBP_SET, pflags + 16 * 32,
                                         nullptr, ph2f);
    head_kernel<<<64, 256>>>(bw2_Wi, bw2_b, Wd, bd, out);
}

// round 15
// speedup vs baseline: 2.1381x; 2.1381x over previous
#include <cuda_runtime.h>
#include <cuda_bf16.h>
#include <mma.h>
#include <cstdint>
#include <cstddef>

using namespace nvcuda;

#define T_SEQ 1024
#define B_SZ  64
// E = 256, H = 256, 4H = 1024

// ---------------- device-global scratch (no allocations) ----------------
__device__ float g_x   [(size_t)B_SZ * T_SEQ * 256];   // gathered embeddings
__device__ float g_xw1f[(size_t)B_SZ * T_SEQ * 1024];  // x @ fw1_Wi
__device__ float g_xw1b[(size_t)B_SZ * T_SEQ * 1024];  // x @ bw1_Wi
__device__ float g_xw2 [(size_t)B_SZ * T_SEQ * 1024];  // x1 @ fw2_Wi
__device__ float g_x1  [(size_t)B_SZ * T_SEQ * 512];   // layer-1 output [fwd|bwd]
__device__ float g_h2f [B_SZ * 256];                   // layer-2 fwd final h
__device__ __nv_bfloat16 g_hb[3][2][B_SZ * 256];       // h double buffers (l1f, l1b, l2)
__device__ unsigned g_flags[24 * 16];                  // per-group: 16 per-CTA flag words

// ---------------- helpers ----------------
__device__ __forceinline__ float tanh_ap(float x) {
    float y;
    asm("tanh.approx.f32 %0, %1;" : "=f"(y) : "f"(x));
    return y;
}
__device__ __forceinline__ float sig_ap(float x) {
    return fmaf(tanh_ap(0.5f * x), 0.5f, 0.5f);
}
__device__ __forceinline__ float sigf(float x) {
    return __fdividef(1.0f, 1.0f + __expf(-x));
}

// ---------------- init: zero release flags (every replay) ----------------
__global__ void init_kernel() {
    int i = blockIdx.x * blockDim.x + threadIdx.x;
    if (i < 24 * 16) g_flags[i] = 0u;
}

// ---------------- embedding gather ----------------
__global__ void gather_kernel(const int* __restrict__ tok, const float* __restrict__ emb) {
    size_t idx = (size_t)blockIdx.x * blockDim.x + threadIdx.x;  // 65536*64 float4
    int row = (int)(idx >> 6);
    int f   = (int)(idx & 63);
    int t   = __ldg(&tok[row]);
    ((float4*)g_x)[idx] = __ldg(&((const float4*)emb)[(size_t)t * 64 + f]);
}

// ---------------- bf16 WMMA GEMM, double-buffered: C[M,N] = A[M,K] @ B[K,N] ----------------
#define GLDA 40
#define GLDB 136
__global__ __launch_bounds__(256, 2) void gemm_bf16(const float* __restrict__ A,
                                                    const float* __restrict__ B,
                                                    float* __restrict__ C,
                                                    int N, int K) {
    __shared__ __nv_bfloat16 As[2][128 * GLDA];
    __shared__ __nv_bfloat16 Bs[2][32 * GLDB];
    const int tid = threadIdx.x;
    const int w   = tid >> 5;
    const int m0  = blockIdx.y * 128;
    const int n0  = blockIdx.x * 128;
    const int wm0 = (w >> 2) * 64;
    const int wn0 = (w & 3) * 32;

    wmma::fragment<wmma::accumulator, 16, 16, 16, float> c[4][2];
    #pragma unroll
    for (int i = 0; i < 4; i++)
        #pragma unroll
        for (int j = 0; j < 2; j++) wmma::fill_fragment(c[i][j], 0.0f);

    float4 ra[4], rb[4];

    #pragma unroll
    for (int p = 0; p < 4; p++) {
        int idx = tid + p * 256;
        int row = idx >> 3, c4 = idx & 7;
        ra[p] = __ldg(&((const float4*)(A + (size_t)(m0 + row) * K))[c4]);
    }
    #pragma unroll
    for (int p = 0; p < 4; p++) {
        int idx = tid + p * 256;
        int row = idx >> 5, c4 = idx & 31;
        rb[p] = __ldg(&((const float4*)(B + (size_t)row * N + n0))[c4]);
    }
    #pragma unroll
    for (int p = 0; p < 4; p++) {
        int idx = tid + p * 256;
        int row = idx >> 3, c4 = idx & 7;
        __nv_bfloat162* dst = (__nv_bfloat162*)(&As[0][row * GLDA + c4 * 4]);
        dst[0] = __floats2bfloat162_rn(ra[p].x, ra[p].y);
        dst[1] = __floats2bfloat162_rn(ra[p].z, ra[p].w);
    }
    #pragma unroll
    for (int p = 0; p < 4; p++) {
        int idx = tid + p * 256;
        int row = idx >> 5, c4 = idx & 31;
        __nv_bfloat162* dst = (__nv_bfloat162*)(&Bs[0][row * GLDB + c4 * 4]);
        dst[0] = __floats2bfloat162_rn(rb[p].x, rb[p].y);
        dst[1] = __floats2bfloat162_rn(rb[p].z, rb[p].w);
    }
    __syncthreads();

    const int nkt = K >> 5;
    for (int kt = 0; kt < nkt; kt++) {
        const int cur = kt & 1;
        const bool more = (kt + 1 < nkt);
        if (more) {
            #pragma unroll
            for (int p = 0; p < 4; p++) {
                int idx = tid + p * 256;
                int row = idx >> 3, c4 = idx & 7;
                ra[p] = __ldg(&((const float4*)(A + (size_t)(m0 + row) * K + (kt + 1) * 32))[c4]);
            }
            #pragma unroll
            for (int p = 0; p < 4; p++) {
                int idx = tid + p * 256;
                int row = idx >> 5, c4 = idx & 31;
                rb[p] = __ldg(&((const float4*)(B + (size_t)((kt + 1) * 32 + row) * N + n0))[c4]);
            }
        }
        #pragma unroll
        for (int kk = 0; kk < 32; kk += 16) {
            wmma::fragment<wmma::matrix_a, 16, 16, 16, __nv_bfloat16, wmma::row_major> a[4];
            wmma::fragment<wmma::matrix_b, 16, 16, 16, __nv_bfloat16, wmma::row_major> b[2];
            #pragma unroll
            for (int i = 0; i < 4; i++)
                wmma::load_matrix_sync(a[i], &As[cur][(wm0 + i * 16) * GLDA + kk], GLDA);
            #pragma unroll
            for (int j = 0; j < 2; j++)
                wmma::load_matrix_sync(b[j], &Bs[cur][kk * GLDB + wn0 + j * 16], GLDB);
            #pragma unroll
            for (int i = 0; i < 4; i++)
                #pragma unroll
                for (int j = 0; j < 2; j++)
                    wmma::mma_sync(c[i][j], a[i], b[j], c[i][j]);
        }
        if (more) {
            const int nxt = cur ^ 1;
            #pragma unroll
            for (int p = 0; p < 4; p++) {
                int idx = tid + p * 256;
                int row = idx >> 3, c4 = idx & 7;
                __nv_bfloat162* dst = (__nv_bfloat162*)(&As[nxt][row * GLDA + c4 * 4]);
                dst[0] = __floats2bfloat162_rn(ra[p].x, ra[p].y);
                dst[1] = __floats2bfloat162_rn(ra[p].z, ra[p].w);
            }
            #pragma unroll
            for (int p = 0; p < 4; p++) {
                int idx = tid + p * 256;
                int row = idx >> 5, c4 = idx & 31;
                __nv_bfloat162* dst = (__nv_bfloat162*)(&Bs[nxt][row * GLDB + c4 * 4]);
                dst[0] = __floats2bfloat162_rn(rb[p].x, rb[p].y);
                dst[1] = __floats2bfloat162_rn(rb[p].z, rb[p].w);
            }
        }
        __syncthreads();
    }
    #pragma unroll
    for (int i = 0; i < 4; i++)
        #pragma unroll
        for (int j = 0; j < 2; j++)
            wmma::store_matrix_sync(C + (size_t)(m0 + wm0 + i * 16) * N + n0 + wn0 + j * 16,
                                    c[i][j], N, wmma::mem_row_major);
}

// ---------------- persistent LSTM scan (R13 data path + per-CTA flag sync) ----------------
// Grid: nDir*128 CTAs, 256 threads. CTA (dir, bg, ng): batch rows bg*8..+8,
// h-cols ng*16..+16 (=> 64 local z-cols). Wh slice in SMEM. h exchanged via
// global bf16 double buffer. Sync: 16 per-CTA flag words per group; producer
// does st.release of its own word (NO atomics); warp 0 lanes 0..15 poll all 16
// in parallel (one L2 round trip per iteration) then __syncthreads broadcasts.
#define WHS_LD 72
#define HS_LD  264
#define ZB_LD  68
#define WHS_BYTES (256 * WHS_LD * 2)          // 36864
#define HS_OFF    WHS_BYTES
#define HS_BYTES  (16 * HS_LD * 2)            // 8448
#define ZB_OFF    (HS_OFF + HS_BYTES)         // 45312
#define ZB_BYTES  (2 * 16 * ZB_LD * 4)        // 8704 (two K-half planes)
#define SCAN_SMEM (ZB_OFF + ZB_BYTES)         // 54016

__global__ __launch_bounds__(256, 2) void scan_kernel(
    const float* __restrict__ xw_f, const float* __restrict__ xw_b,
    const float* __restrict__ Wh_f, const float* __restrict__ Wh_b,
    const float* __restrict__ b_f,  const float* __restrict__ b_b,
    __nv_bfloat16* hb_base, unsigned* flags_base,
    float* x1out, float* h2out) {
    extern __shared__ char sm[];
    __nv_bfloat16* Whs = (__nv_bfloat16*)sm;
    __nv_bfloat16* hs  = (__nv_bfloat16*)(sm + HS_OFF);
    float*         zb  = (float*)(sm + ZB_OFF);

    const int tid = threadIdx.x;
    const int w   = tid >> 5;
    const int lane = tid & 31;
    const int dir = blockIdx.x >> 7;              // scan2 grid=128 -> always 0
    const int sub = blockIdx.x & 127;
    const int bg  = sub >> 4, ng = sub & 15;
    const int r0  = bg * 8, hc0 = ng * 16;

    const float* xw   = dir ? xw_b : xw_f;
    const float* Whg  = dir ? Wh_b : Wh_f;
    const float* bias = dir ? b_b  : b_f;
    __nv_bfloat16* hb = hb_base + (size_t)dir * 2 * (B_SZ * 256);
    unsigned* flagg = flags_base + (dir * 8 + bg) * 16;   // 16 per-CTA flags (64B)

    // zero hs once (rows 8..15 stay zero forever -> M padded to 16)
    for (int i = tid; i < 16 * HS_LD; i += 256) hs[i] = __float2bfloat16(0.f);
    // stage Wh slice bf16: Whs[k][c], c = gate*16+j -> global col gate*256+hc0+j
    for (int i = tid; i < 256 * 64; i += 256) {
        int k = i >> 6, cc = i & 63;
        int gt = cc >> 4, j = cc & 15;
        Whs[k * WHS_LD + cc] =
            __float2bfloat16_rn(__ldg(&Whg[(size_t)k * 1024 + gt * 256 + hc0 + j]));
    }

    // h-load role: row lrow (0..7), 8 bf16 (16B) per thread
    const int lrow = tid >> 5;
    const int lcol = (tid & 31) * 8;
    // MMA role: K-half q, local col base n0
    const int q  = w >> 2;
    const int n0 = (w & 3) * 16;
    // gate role (tid < 128): row gr, h-col gj
    const int gr = tid >> 4, gj = tid & 15;
    const int xwbase = hc0 + gj;
    float bi = 0.f, bfv = 0.f, bgv = 0.f, bo = 0.f;
    if (tid < 128) {
        bi  = __ldg(&bias[0 * 256 + xwbase]);
        bfv = __ldg(&bias[1 * 256 + xwbase]);
        bgv = __ldg(&bias[2 * 256 + xwbase]);
        bo  = __ldg(&bias[3 * 256 + xwbase]);
    }
    float c_state = 0.0f;
    const float* xwrow = xw + (size_t)(r0 + gr) * T_SEQ * 1024 + xwbase;
    __syncthreads();

    // prefetch xw for steps 0 and 1 (2-deep register pipeline)
    float4 xv0 = make_float4(0.f, 0.f, 0.f, 0.f);
    float4 xv1 = make_float4(0.f, 0.f, 0.f, 0.f);
    if (tid < 128) {
        int ta = dir ? (T_SEQ - 1) : 0;
        int tb = dir ? (T_SEQ - 2) : 1;
        const float* pa = xwrow + (size_t)ta * 1024;
        const float* pb = xwrow + (size_t)tb * 1024;
        xv0.x = __ldcs(pa); xv0.y = __ldcs(pa + 256); xv0.z = __ldcs(pa + 512); xv0.w = __ldcs(pa + 768);
        xv1.x = __ldcs(pb); xv1.y = __ldcs(pb + 256); xv1.z = __ldcs(pb + 512); xv1.w = __ldcs(pb + 768);
    }

    // one scan step; consumes xc (xw for step s), refills it with step s+2
    auto do_step = [&](int s, float4& xc) -> bool {
        if (s > 0) {
            // warp 0: lanes 0..15 poll the 16 per-CTA flags in parallel (acquire)
            if (w == 0) {
                const unsigned tgt = (unsigned)s;
                unsigned v = tgt;
                do {
                    if (lane < 16)
                        asm volatile("ld.acquire.gpu.global.u32 %0, [%1];"
                                     : "=r"(v) : "l"(flagg + lane) : "memory");
                } while (__any_sync(0xffffffffu, v < tgt));
            }
            __syncthreads();
            // load h(s) [8 rows x 256] bf16 from L2 into hs rows 0..7
            {
                const __nv_bfloat16* hread = hb + (s & 1) * (B_SZ * 256) + (r0 + lrow) * 256 + lcol;
                uint4 hv = __ldcg((const uint4*)hread);
                *(uint4*)(hs + lrow * HS_LD + lcol) = hv;
            }
            __syncthreads();
            // K-split MMA: warp (q, n0); 8-deep chain over its 128 k
            {
                wmma::fragment<wmma::accumulator, 16, 16, 16, float> acc;
                wmma::fill_fragment(acc, 0.0f);
                const int kbase = q * 128;
                #pragma unroll
                for (int kt = 0; kt < 8; kt++) {
                    wmma::fragment<wmma::matrix_a, 16, 16, 16, __nv_bfloat16, wmma::row_major> a;
                    wmma::fragment<wmma::matrix_b, 16, 16, 16, __nv_bfloat16, wmma::row_major> b;
                    const int kk = kbase + kt * 16;
                    wmma::load_matrix_sync(a, hs + kk, HS_LD);
                    wmma::load_matrix_sync(b, Whs + kk * WHS_LD + n0, WHS_LD);
                    wmma::mma_sync(acc, a, b, acc);
                }
                wmma::store_matrix_sync(zb + q * (16 * ZB_LD) + n0, acc, ZB_LD, wmma::mem_row_major);
            }
        }
        __syncthreads();

        const bool last = (s == T_SEQ - 1);
        float hval = 0.f;
        if (tid < 128) {
            float zi = bi + xc.x, zf = bfv + xc.y, zg = bgv + xc.z, zo = bo + xc.w;
            if (s > 0) {
                const float* z0 = zb + gr * ZB_LD;
                const float* z1 = z0 + 16 * ZB_LD;
                zi += z0[gj]      + z1[gj];
                zf += z0[16 + gj] + z1[16 + gj];
                zg += z0[32 + gj] + z1[32 + gj];
                zo += z0[48 + gj] + z1[48 + gj];
            }
            c_state = sig_ap(zf) * c_state + sig_ap(zi) * tanh_ap(zg);
            hval = sig_ap(zo) * tanh_ap(c_state);
            if (!last) {
                // publish h(s+1) — the ONLY store the release has to order
                __nv_bfloat16 hv = __float2bfloat16_rn(hval);
                __stcg((__nv_bfloat16*)(hb + ((s + 1) & 1) * (B_SZ * 256) + (r0 + gr) * 256 + hc0 + gj), hv);
            }
        }
        const int t_in = dir ? (T_SEQ - 1 - s) : s;
        if (last) {
            if (tid < 128) {
                if (x1out)
                    __stcg(x1out + ((size_t)(r0 + gr) * T_SEQ + t_in) * 512 + dir * 256 + hc0 + gj, hval);
                if (h2out)
                    h2out[(r0 + gr) * 256 + hc0 + gj] = hval;
            }
            return true;
        }
        __syncthreads();   // all h stores issued before the release store
        if (tid == 0)
            asm volatile("st.release.gpu.global.u32 [%0], %1;"
                         :: "l"(flagg + ng), "r"((unsigned)(s + 1)) : "memory");
        // post-release: bulk output store + 2-ahead prefetch (off the release path)
        if (tid < 128) {
            if (x1out)
                __stcg(x1out + ((size_t)(r0 + gr) * T_SEQ + t_in) * 512 + dir * 256 + hc0 + gj, hval);
            if (s + 2 < T_SEQ) {
                int tn = dir ? (T_SEQ - 1 - (s + 2)) : (s + 2);
                const float* p = xwrow + (size_t)tn * 1024;
                xc.x = __ldcs(p); xc.y = __ldcs(p + 256); xc.z = __ldcs(p + 512); xc.w = __ldcs(p + 768);
            }
        }
        return false;
    };

    for (int s = 0; s < T_SEQ; s += 2) {
        if (do_step(s, xv0)) break;
        if (do_step(s + 1, xv1)) break;
    }
}

// ---------------- head: layer-2 bwd single step + final dot + sigmoid ----------------
__global__ __launch_bounds__(256) void head_kernel(const float* __restrict__ Wi,
                                                   const float* __restrict__ b2,
                                                   const float* __restrict__ Wd,
                                                   const float* __restrict__ bd,
                                                   float* __restrict__ out) {
    __shared__ float xr[512];
    __shared__ float z[1024];
    __shared__ float red[8];
    const int b = blockIdx.x, tid = threadIdx.x;
    const float* xrow = g_x1 + ((size_t)b * T_SEQ + (T_SEQ - 1)) * 512;
    xr[tid] = xrow[tid];
    xr[tid + 256] = xrow[tid + 256];
    __syncthreads();
    const int c0 = tid * 4;
    float4 acc = *(const float4*)(b2 + c0);
    for (int k = 0; k < 512; k++) {
        float xv = xr[k];
        float4 wv = __ldg((const float4*)(Wi + (size_t)k * 1024 + c0));
        acc.x = fmaf(xv, wv.x, acc.x);
        acc.y = fmaf(xv, wv.y, acc.y);
        acc.z = fmaf(xv, wv.z, acc.z);
        acc.w = fmaf(xv, wv.w, acc.w);
    }
    *(float4*)(z + c0) = acc;
    __syncthreads();
    float zi = z[tid], zg = z[512 + tid], zo = z[768 + tid];
    float cst = sigf(zi) * tanhf(zg);           // c0 = 0 so forget term vanishes
    float h2b = sigf(zo) * tanhf(cst);
    float pl = g_h2f[b * 256 + tid] * __ldg(&Wd[tid]) + h2b * __ldg(&Wd[256 + tid]);
    #pragma unroll
    for (int off = 16; off; off >>= 1) pl += __shfl_down_sync(0xffffffffu, pl, off);
    if ((tid & 31) == 0) red[tid >> 5] = pl;
    __syncthreads();
    if (tid == 0) {
        float ssum = 0.f;
        #pragma unroll
        for (int q = 0; q < 8; q++) ssum += red[q];
        out[b] = sigf(ssum + bd[0]);
    }
}

// ---------------- launch ----------------
extern "C" void kernel_launch(void* const* d_in, const int* in_sizes, int n_in,
                              void* d_out, int out_size) {
    const int*   tokens = (const int*)  d_in[0];
    const float* embed  = (const float*)d_in[1];
    const float* fw1_Wi = (const float*)d_in[2];
    const float* fw1_Wh = (const float*)d_in[3];
    const float* fw1_b  = (const float*)d_in[4];
    const float* bw1_Wi = (const float*)d_in[5];
    const float* bw1_Wh = (const float*)d_in[6];
    const float* bw1_b  = (const float*)d_in[7];
    const float* fw2_Wi = (const float*)d_in[8];
    const float* fw2_Wh = (const float*)d_in[9];
    const float* fw2_b  = (const float*)d_in[10];
    const float* bw2_Wi = (const float*)d_in[11];
    const float* bw2_b  = (const float*)d_in[13];
    const float* Wd     = (const float*)d_in[14];
    const float* bd     = (const float*)d_in[15];
    float* out = (float*)d_out;

    float *px, *pxw1f, *pxw1b, *pxw2, *px1, *ph2f;
    __nv_bfloat16* phb;
    unsigned* pflags;
    cudaGetSymbolAddress((void**)&px,    g_x);
    cudaGetSymbolAddress((void**)&pxw1f, g_xw1f);
    cudaGetSymbolAddress((void**)&pxw1b, g_xw1b);
    cudaGetSymbolAddress((void**)&pxw2,  g_xw2);
    cudaGetSymbolAddress((void**)&px1,   g_x1);
    cudaGetSymbolAddress((void**)&ph2f,  g_h2f);
    cudaGetSymbolAddress((void**)&phb,   g_hb);
    cudaGetSymbolAddress((void**)&pflags, g_flags);

    cudaFuncSetAttribute(scan_kernel, cudaFuncAttributeMaxDynamicSharedMemorySize, SCAN_SMEM);

    init_kernel<<<2, 256>>>();
    gather_kernel<<<16384, 256>>>(tokens, embed);
    gemm_bf16<<<dim3(8, 512), 256>>>(px, fw1_Wi, pxw1f, 1024, 256);
    gemm_bf16<<<dim3(8, 512), 256>>>(px, bw1_Wi, pxw1b, 1024, 256);
    scan_kernel<<<256, 256, SCAN_SMEM>>>(pxw1f, pxw1b, fw1_Wh, bw1_Wh, fw1_b, bw1_b,
                                         phb, pflags, px1, nullptr);
    gemm_bf16<<<dim3(8, 512), 256>>>(px1, fw2_Wi, pxw2, 1024, 512);
    scan_kernel<<<128, 256, SCAN_SMEM>>>(pxw2, pxw2, fw2_Wh, fw2_Wh, fw2_b, fw2_b,
                                         phb + (size_t)2 * 2 * (B_SZ * 256), pflags + 16 * 16,
                                         nullptr, ph2f);
    head_kernel<<<64, 256>>>(bw2_Wi, bw2_b, Wd, bd, out);
}

// round 16
// speedup vs baseline: 2.4963x; 1.1675x over previous
#include <cuda_runtime.h>
#include <cuda_bf16.h>
#include <mma.h>
#include <cstdint>
#include <cstddef>

using namespace nvcuda;

#define T_SEQ 1024
#define B_SZ  64
// E = 256, H = 256, 4H = 1024

// ---------------- device-global scratch (no allocations) ----------------
__device__ __nv_bfloat16 g_x [(size_t)B_SZ * T_SEQ * 256];   // gathered embeddings (bf16)
__device__ float g_xw1f[(size_t)B_SZ * T_SEQ * 1024];  // x @ fw1_Wi
__device__ float g_xw1b[(size_t)B_SZ * T_SEQ * 1024];  // x @ bw1_Wi
__device__ float g_xw2 [(size_t)B_SZ * T_SEQ * 1024];  // x1 @ fw2_Wi
__device__ __nv_bfloat16 g_x1[(size_t)B_SZ * T_SEQ * 512];   // layer-1 output (bf16)
__device__ float g_h2f [B_SZ * 256];                   // layer-2 fwd final h
__device__ __nv_bfloat16 g_hb[3][2][B_SZ * 256];       // h double buffers (l1f, l1b, l2)
__device__ unsigned g_ctrs[32];                        // group barrier counters

// ---------------- helpers ----------------
__device__ __forceinline__ float tanh_ap(float x) {
    float y;
    asm("tanh.approx.f32 %0, %1;" : "=f"(y) : "f"(x));
    return y;
}
__device__ __forceinline__ float sig_ap(float x) {
    return fmaf(tanh_ap(0.5f * x), 0.5f, 0.5f);
}
__device__ __forceinline__ float sigf(float x) {
    return __fdividef(1.0f, 1.0f + __expf(-x));
}

// ---------------- dummy: shifts ncu capture slot (-s 5) onto scan1 ----------------
__global__ void dummy_kernel() {}

// ---------------- init: zero barrier counters (every replay) ----------------
__global__ void init_kernel() {
    int i = threadIdx.x;
    if (i < 32) g_ctrs[i] = 0u;
}

// ---------------- embedding gather -> bf16 ----------------
__global__ void gather_kernel(const int* __restrict__ tok, const float* __restrict__ emb) {
    size_t idx = (size_t)blockIdx.x * blockDim.x + threadIdx.x;  // over 2M chunks of 8
    int row = (int)(idx >> 5);          // token row (B*T)
    int f   = (int)(idx & 31);          // 8-elem chunk within 256
    int t   = __ldg(&tok[row]);
    const float4* src = (const float4*)(emb + (size_t)t * 256 + f * 8);
    float4 a = __ldg(src);
    float4 b = __ldg(src + 1);
    uint4 o;
    __nv_bfloat162 p0 = __floats2bfloat162_rn(a.x, a.y);
    __nv_bfloat162 p1 = __floats2bfloat162_rn(a.z, a.w);
    __nv_bfloat162 p2 = __floats2bfloat162_rn(b.x, b.y);
    __nv_bfloat162 p3 = __floats2bfloat162_rn(b.z, b.w);
    o.x = *reinterpret_cast<unsigned*>(&p0);
    o.y = *reinterpret_cast<unsigned*>(&p1);
    o.z = *reinterpret_cast<unsigned*>(&p2);
    o.w = *reinterpret_cast<unsigned*>(&p3);
    ((uint4*)g_x)[idx] = o;
}

// ---------------- bf16 GEMM (A already bf16): C[M,N] = A[M,K] @ B[K,N] ----------------
#define GLDA 40
#define GLDB 136
__global__ __launch_bounds__(256, 2) void gemm_bf16(const __nv_bfloat16* __restrict__ A,
                                                    const float* __restrict__ B,
                                                    float* __restrict__ C,
                                                    int N, int K) {
    __shared__ __nv_bfloat16 As[2][128 * GLDA];
    __shared__ __nv_bfloat16 Bs[2][32 * GLDB];
    const int tid = threadIdx.x;
    const int w   = tid >> 5;
    const int m0  = blockIdx.y * 128;
    const int n0  = blockIdx.x * 128;
    const int wm0 = (w >> 2) * 64;
    const int wn0 = (w & 3) * 32;

    wmma::fragment<wmma::accumulator, 16, 16, 16, float> c[4][2];
    #pragma unroll
    for (int i = 0; i < 4; i++)
        #pragma unroll
        for (int j = 0; j < 2; j++) wmma::fill_fragment(c[i][j], 0.0f);

    uint4  ra[2];
    float4 rb[4];

    // prologue: tile 0
    #pragma unroll
    for (int p = 0; p < 2; p++) {
        int idx = tid + p * 256;
        int row = idx >> 2, c8 = idx & 3;    // 128 rows x 4 chunks of 8 bf16
        ra[p] = __ldg(&((const uint4*)(A + (size_t)(m0 + row) * K))[c8]);
    }
    #pragma unroll
    for (int p = 0; p < 4; p++) {
        int idx = tid + p * 256;
        int row = idx >> 5, c4 = idx & 31;
        rb[p] = __ldg(&((const float4*)(B + (size_t)row * N + n0))[c4]);
    }
    #pragma unroll
    for (int p = 0; p < 2; p++) {
        int idx = tid + p * 256;
        int row = idx >> 2, c8 = idx & 3;
        *(uint4*)(&As[0][row * GLDA + c8 * 8]) = ra[p];
    }
    #pragma unroll
    for (int p = 0; p < 4; p++) {
        int idx = tid + p * 256;
        int row = idx >> 5, c4 = idx & 31;
        __nv_bfloat162* dst = (__nv_bfloat162*)(&Bs[0][row * GLDB + c4 * 4]);
        dst[0] = __floats2bfloat162_rn(rb[p].x, rb[p].y);
        dst[1] = __floats2bfloat162_rn(rb[p].z, rb[p].w);
    }
    __syncthreads();

    const int nkt = K >> 5;
    for (int kt = 0; kt < nkt; kt++) {
        const int cur = kt & 1;
        const bool more = (kt + 1 < nkt);
        if (more) {
            #pragma unroll
            for (int p = 0; p < 2; p++) {
                int idx = tid + p * 256;
                int row = idx >> 2, c8 = idx & 3;
                ra[p] = __ldg(&((const uint4*)(A + (size_t)(m0 + row) * K + (kt + 1) * 32))[c8]);
            }
            #pragma unroll
            for (int p = 0; p < 4; p++) {
                int idx = tid + p * 256;
                int row = idx >> 5, c4 = idx & 31;
                rb[p] = __ldg(&((const float4*)(B + (size_t)((kt + 1) * 32 + row) * N + n0))[c4]);
            }
        }
        #pragma unroll
        for (int kk = 0; kk < 32; kk += 16) {
            wmma::fragment<wmma::matrix_a, 16, 16, 16, __nv_bfloat16, wmma::row_major> a[4];
            wmma::fragment<wmma::matrix_b, 16, 16, 16, __nv_bfloat16, wmma::row_major> b[2];
            #pragma unroll
            for (int i = 0; i < 4; i++)
                wmma::load_matrix_sync(a[i], &As[cur][(wm0 + i * 16) * GLDA + kk], GLDA);
            #pragma unroll
            for (int j = 0; j < 2; j++)
                wmma::load_matrix_sync(b[j], &Bs[cur][kk * GLDB + wn0 + j * 16], GLDB);
            #pragma unroll
            for (int i = 0; i < 4; i++)
                #pragma unroll
                for (int j = 0; j < 2; j++)
                    wmma::mma_sync(c[i][j], a[i], b[j], c[i][j]);
        }
        if (more) {
            const int nxt = cur ^ 1;
            #pragma unroll
            for (int p = 0; p < 2; p++) {
                int idx = tid + p * 256;
                int row = idx >> 2, c8 = idx & 3;
                *(uint4*)(&As[nxt][row * GLDA + c8 * 8]) = ra[p];
            }
            #pragma unroll
            for (int p = 0; p < 4; p++) {
                int idx = tid + p * 256;
                int row = idx >> 5, c4 = idx & 31;
                __nv_bfloat162* dst = (__nv_bfloat162*)(&Bs[nxt][row * GLDB + c4 * 4]);
                dst[0] = __floats2bfloat162_rn(rb[p].x, rb[p].y);
                dst[1] = __floats2bfloat162_rn(rb[p].z, rb[p].w);
            }
        }
        __syncthreads();
    }
    #pragma unroll
    for (int i = 0; i < 4; i++)
        #pragma unroll
        for (int j = 0; j < 2; j++)
            wmma::store_matrix_sync(C + (size_t)(m0 + wm0 + i * 16) * N + n0 + wn0 + j * 16,
                                    c[i][j], N, wmma::mem_row_major);
}

// ---------------- persistent LSTM scan (R13: counter sync + 2-ahead prefetch) ----------------
#define WHS_LD 72
#define HS_LD  264
#define ZB_LD  68
#define WHS_BYTES (256 * WHS_LD * 2)          // 36864
#define HS_OFF    WHS_BYTES
#define HS_BYTES  (16 * HS_LD * 2)            // 8448
#define ZB_OFF    (HS_OFF + HS_BYTES)         // 45312
#define ZB_BYTES  (2 * 16 * ZB_LD * 4)        // 8704 (two K-half planes)
#define SCAN_SMEM (ZB_OFF + ZB_BYTES)         // 54016

__global__ __launch_bounds__(256, 2) void scan_kernel(
    const float* __restrict__ xw_f, const float* __restrict__ xw_b,
    const float* __restrict__ Wh_f, const float* __restrict__ Wh_b,
    const float* __restrict__ b_f,  const float* __restrict__ b_b,
    __nv_bfloat16* hb_base, unsigned* ctrs,
    __nv_bfloat16* x1out, float* h2out) {
    extern __shared__ char sm[];
    __nv_bfloat16* Whs = (__nv_bfloat16*)sm;
    __nv_bfloat16* hs  = (__nv_bfloat16*)(sm + HS_OFF);
    float*         zb  = (float*)(sm + ZB_OFF);

    const int tid = threadIdx.x;
    const int w   = tid >> 5;
    const int dir = blockIdx.x >> 7;              // scan2 grid=128 -> always 0
    const int sub = blockIdx.x & 127;
    const int bg  = sub >> 4, ng = sub & 15;
    const int r0  = bg * 8, hc0 = ng * 16;

    const float* xw   = dir ? xw_b : xw_f;
    const float* Whg  = dir ? Wh_b : Wh_f;
    const float* bias = dir ? b_b  : b_f;
    __nv_bfloat16* hb = hb_base + (size_t)dir * 2 * (B_SZ * 256);
    unsigned* ctr = ctrs + dir * 8 + bg;

    // zero hs once (rows 8..15 stay zero forever -> M padded to 16)
    for (int i = tid; i < 16 * HS_LD; i += 256) hs[i] = __float2bfloat16(0.f);
    // stage Wh slice bf16: Whs[k][c], c = gate*16+j -> global col gate*256+hc0+j
    for (int i = tid; i < 256 * 64; i += 256) {
        int k = i >> 6, cc = i & 63;
        int gt = cc >> 4, j = cc & 15;
        Whs[k * WHS_LD + cc] =
            __float2bfloat16_rn(__ldg(&Whg[(size_t)k * 1024 + gt * 256 + hc0 + j]));
    }

    // h-load role: row lrow (0..7), 8 bf16 (16B) per thread
    const int lrow = tid >> 5;
    const int lcol = (tid & 31) * 8;
    // MMA role: K-half q, local col base n0
    const int q  = w >> 2;
    const int n0 = (w & 3) * 16;
    // gate role (tid < 128): row gr, h-col gj
    const int gr = tid >> 4, gj = tid & 15;
    const int xwbase = hc0 + gj;
    float bi = 0.f, bfv = 0.f, bgv = 0.f, bo = 0.f;
    if (tid < 128) {
        bi  = __ldg(&bias[0 * 256 + xwbase]);
        bfv = __ldg(&bias[1 * 256 + xwbase]);
        bgv = __ldg(&bias[2 * 256 + xwbase]);
        bo  = __ldg(&bias[3 * 256 + xwbase]);
    }
    float c_state = 0.0f;
    const float* xwrow = xw + (size_t)(r0 + gr) * T_SEQ * 1024 + xwbase;
    __syncthreads();

    // prefetch xw for steps 0 and 1 (2-deep register pipeline)
    float4 xv0 = make_float4(0.f, 0.f, 0.f, 0.f);
    float4 xv1 = make_float4(0.f, 0.f, 0.f, 0.f);
    if (tid < 128) {
        int ta = dir ? (T_SEQ - 1) : 0;
        int tb = dir ? (T_SEQ - 2) : 1;
        const float* pa = xwrow + (size_t)ta * 1024;
        const float* pb = xwrow + (size_t)tb * 1024;
        xv0.x = __ldcs(pa); xv0.y = __ldcs(pa + 256); xv0.z = __ldcs(pa + 512); xv0.w = __ldcs(pa + 768);
        xv1.x = __ldcs(pb); xv1.y = __ldcs(pb + 256); xv1.z = __ldcs(pb + 512); xv1.w = __ldcs(pb + 768);
    }

    // one scan step; consumes xc (xw for step s), refills it with step s+2
    auto do_step = [&](int s, float4& xc) -> bool {
        if (s > 0) {
            // wait for all 16 group CTAs to have published h(s)
            if (tid == 0) {
                const unsigned tgt = 16u * (unsigned)s;
                unsigned v;
                do {
                    asm volatile("ld.acquire.gpu.global.u32 %0, [%1];" : "=r"(v) : "l"(ctr) : "memory");
                } while (v < tgt);
            }
            __syncthreads();
            // load h(s) [8 rows x 256] bf16 from L2 into hs rows 0..7
            {
                const __nv_bfloat16* hread = hb + (s & 1) * (B_SZ * 256) + (r0 + lrow) * 256 + lcol;
                uint4 hv = __ldcg((const uint4*)hread);
                *(uint4*)(hs + lrow * HS_LD + lcol) = hv;
            }
            __syncthreads();
            // K-split MMA: warp (q, n0); 8-deep chain over its 128 k
            {
                wmma::fragment<wmma::accumulator, 16, 16, 16, float> acc;
                wmma::fill_fragment(acc, 0.0f);
                const int kbase = q * 128;
                #pragma unroll
                for (int kt = 0; kt < 8; kt++) {
                    wmma::fragment<wmma::matrix_a, 16, 16, 16, __nv_bfloat16, wmma::row_major> a;
                    wmma::fragment<wmma::matrix_b, 16, 16, 16, __nv_bfloat16, wmma::row_major> b;
                    const int kk = kbase + kt * 16;
                    wmma::load_matrix_sync(a, hs + kk, HS_LD);
                    wmma::load_matrix_sync(b, Whs + kk * WHS_LD + n0, WHS_LD);
                    wmma::mma_sync(acc, a, b, acc);
                }
                wmma::store_matrix_sync(zb + q * (16 * ZB_LD) + n0, acc, ZB_LD, wmma::mem_row_major);
            }
        }
        __syncthreads();

        const bool last = (s == T_SEQ - 1);
        __nv_bfloat16 hv16 = __float2bfloat16(0.f);
        float hval = 0.f;
        if (tid < 128) {
            float zi = bi + xc.x, zf = bfv + xc.y, zg = bgv + xc.z, zo = bo + xc.w;
            if (s > 0) {
                const float* z0 = zb + gr * ZB_LD;
                const float* z1 = z0 + 16 * ZB_LD;
                zi += z0[gj]      + z1[gj];
                zf += z0[16 + gj] + z1[16 + gj];
                zg += z0[32 + gj] + z1[32 + gj];
                zo += z0[48 + gj] + z1[48 + gj];
            }
            c_state = sig_ap(zf) * c_state + sig_ap(zi) * tanh_ap(zg);
            hval = sig_ap(zo) * tanh_ap(c_state);
            hv16 = __float2bfloat16_rn(hval);
            if (!last) {
                // publish h(s+1) — the ONLY store the release has to order
                __stcg((__nv_bfloat16*)(hb + ((s + 1) & 1) * (B_SZ * 256) + (r0 + gr) * 256 + hc0 + gj), hv16);
            }
        }
        const int t_in = dir ? (T_SEQ - 1 - s) : s;
        if (last) {
            if (tid < 128) {
                if (x1out)
                    __stcg(x1out + ((size_t)(r0 + gr) * T_SEQ + t_in) * 512 + dir * 256 + hc0 + gj, hv16);
                if (h2out)
                    h2out[(r0 + gr) * 256 + hc0 + gj] = hval;
            }
            return true;
        }
        __syncthreads();   // all h stores issued before tid0's release
        if (tid == 0)
            asm volatile("red.release.gpu.global.add.u32 [%0], %1;" :: "l"(ctr), "r"(1u) : "memory");
        // post-release: bulk output store + 2-ahead prefetch (off the release path)
        if (tid < 128) {
            if (x1out)
                __stcg(x1out + ((size_t)(r0 + gr) * T_SEQ + t_in) * 512 + dir * 256 + hc0 + gj, hv16);
            if (s + 2 < T_SEQ) {
                int tn = dir ? (T_SEQ - 1 - (s + 2)) : (s + 2);
                const float* p = xwrow + (size_t)tn * 1024;
                xc.x = __ldcs(p); xc.y = __ldcs(p + 256); xc.z = __ldcs(p + 512); xc.w = __ldcs(p + 768);
            }
        }
        return false;
    };

    for (int s = 0; s < T_SEQ; s += 2) {
        if (do_step(s, xv0)) break;
        if (do_step(s + 1, xv1)) break;
    }
}

// ---------------- head: layer-2 bwd single step + final dot + sigmoid ----------------
__global__ __launch_bounds__(256) void head_kernel(const float* __restrict__ Wi,
                                                   const float* __restrict__ b2,
                                                   const float* __restrict__ Wd,
                                                   const float* __restrict__ bd,
                                                   float* __restrict__ out) {
    __shared__ float xr[512];
    __shared__ float z[1024];
    __shared__ float red[8];
    const int b = blockIdx.x, tid = threadIdx.x;
    const __nv_bfloat16* xrow = g_x1 + ((size_t)b * T_SEQ + (T_SEQ - 1)) * 512;
    xr[tid] = __bfloat162float(xrow[tid]);
    xr[tid + 256] = __bfloat162float(xrow[tid + 256]);
    __syncthreads();
    const int c0 = tid * 4;
    float4 acc = *(const float4*)(b2 + c0);
    for (int k = 0; k < 512; k++) {
        float xv = xr[k];
        float4 wv = __ldg((const float4*)(Wi + (size_t)k * 1024 + c0));
        acc.x = fmaf(xv, wv.x, acc.x);
        acc.y = fmaf(xv, wv.y, acc.y);
        acc.z = fmaf(xv, wv.z, acc.z);
        acc.w = fmaf(xv, wv.w, acc.w);
    }
    *(float4*)(z + c0) = acc;
    __syncthreads();
    float zi = z[tid], zg = z[512 + tid], zo = z[768 + tid];
    float cst = sigf(zi) * tanhf(zg);           // c0 = 0 so forget term vanishes
    float h2b = sigf(zo) * tanhf(cst);
    float pl = g_h2f[b * 256 + tid] * __ldg(&Wd[tid]) + h2b * __ldg(&Wd[256 + tid]);
    #pragma unroll
    for (int off = 16; off; off >>= 1) pl += __shfl_down_sync(0xffffffffu, pl, off);
    if ((tid & 31) == 0) red[tid >> 5] = pl;
    __syncthreads();
    if (tid == 0) {
        float ssum = 0.f;
        #pragma unroll
        for (int q = 0; q < 8; q++) ssum += red[q];
        out[b] = sigf(ssum + bd[0]);
    }
}

// ---------------- launch ----------------
extern "C" void kernel_launch(void* const* d_in, const int* in_sizes, int n_in,
                              void* d_out, int out_size) {
    const int*   tokens = (const int*)  d_in[0];
    const float* embed  = (const float*)d_in[1];
    const float* fw1_Wi = (const float*)d_in[2];
    const float* fw1_Wh = (const float*)d_in[3];
    const float* fw1_b  = (const float*)d_in[4];
    const float* bw1_Wi = (const float*)d_in[5];
    const float* bw1_Wh = (const float*)d_in[6];
    const float* bw1_b  = (const float*)d_in[7];
    const float* fw2_Wi = (const float*)d_in[8];
    const float* fw2_Wh = (const float*)d_in[9];
    const float* fw2_b  = (const float*)d_in[10];
    const float* bw2_Wi = (const float*)d_in[11];
    const float* bw2_b  = (const float*)d_in[13];
    const float* Wd     = (const float*)d_in[14];
    const float* bd     = (const float*)d_in[15];
    float* out = (float*)d_out;

    float *pxw1f, *pxw1b, *pxw2, *ph2f;
    __nv_bfloat16 *px, *px1, *phb;
    unsigned* pctrs;
    cudaGetSymbolAddress((void**)&px,    g_x);
    cudaGetSymbolAddress((void**)&pxw1f, g_xw1f);
    cudaGetSymbolAddress((void**)&pxw1b, g_xw1b);
    cudaGetSymbolAddress((void**)&pxw2,  g_xw2);
    cudaGetSymbolAddress((void**)&px1,   g_x1);
    cudaGetSymbolAddress((void**)&ph2f,  g_h2f);
    cudaGetSymbolAddress((void**)&phb,   g_hb);
    cudaGetSymbolAddress((void**)&pctrs, g_ctrs);

    cudaFuncSetAttribute(scan_kernel, cudaFuncAttributeMaxDynamicSharedMemorySize, SCAN_SMEM);

    dummy_kernel<<<1, 32>>>();                      // shifts ncu -s 5 onto scan1
    init_kernel<<<1, 32>>>();
    gather_kernel<<<8192, 256>>>(tokens, embed);
    gemm_bf16<<<dim3(8, 512), 256>>>(px, fw1_Wi, pxw1f, 1024, 256);
    gemm_bf16<<<dim3(8, 512), 256>>>(px, bw1_Wi, pxw1b, 1024, 256);
    scan_kernel<<<256, 256, SCAN_SMEM>>>(pxw1f, pxw1b, fw1_Wh, bw1_Wh, fw1_b, bw1_b,
                                         phb, pctrs, px1, nullptr);
    gemm_bf16<<<dim3(8, 512), 256>>>(px1, fw2_Wi, pxw2, 1024, 512);
    scan_kernel<<<128, 256, SCAN_SMEM>>>(pxw2, pxw2, fw2_Wh, fw2_Wh, fw2_b, fw2_b,
                                         phb + (size_t)2 * 2 * (B_SZ * 256), pctrs + 16,
                                         nullptr, ph2f);
    head_kernel<<<64, 256>>>(bw2_Wi, bw2_b, Wd, bd, out);
}

// round 17
// speedup vs baseline: 2.5183x; 1.0088x over previous
#include <cuda_runtime.h>
#include <cuda_bf16.h>
#include <mma.h>
#include <cstdint>
#include <cstddef>

using namespace nvcuda;

#define T_SEQ 1024
#define B_SZ  64
// E = 256, H = 256, 4H = 1024

// ---------------- device-global scratch (no allocations) ----------------
__device__ __nv_bfloat16 g_x [(size_t)B_SZ * T_SEQ * 256];   // gathered embeddings (bf16)
__device__ float g_xw1f[(size_t)B_SZ * T_SEQ * 1024];  // x @ fw1_Wip (gate-interleaved)
__device__ float g_xw1b[(size_t)B_SZ * T_SEQ * 1024];
__device__ float g_xw2 [(size_t)B_SZ * T_SEQ * 1024];
__device__ __nv_bfloat16 g_x1[(size_t)B_SZ * T_SEQ * 512];   // layer-1 output (bf16)
__device__ float g_h2f [B_SZ * 256];                   // layer-2 fwd final h
__device__ __nv_bfloat16 g_hb[3][2][B_SZ * 256];       // h double buffers (l1f, l1b, l2)
__device__ unsigned g_ctrs[32];                        // group barrier counters
__device__ float g_wip1f[256 * 1024];                  // permuted Wi (gate-interleaved cols)
__device__ float g_wip1b[256 * 1024];
__device__ float g_wip2 [512 * 1024];
__device__ float g_bp[3][1024];                        // permuted biases

// ---------------- helpers ----------------
__device__ __forceinline__ float tanh_ap(float x) {
    float y;
    asm("tanh.approx.f32 %0, %1;" : "=f"(y) : "f"(x));
    return y;
}
__device__ __forceinline__ float sig_ap(float x) {
    return fmaf(tanh_ap(0.5f * x), 0.5f, 0.5f);
}
__device__ __forceinline__ float sigf(float x) {
    return __fdividef(1.0f, 1.0f + __expf(-x));
}

// ---------------- init: zero barrier counters (every replay) ----------------
__global__ void init_kernel() {
    int i = threadIdx.x;
    if (i < 32) g_ctrs[i] = 0u;
}

// ---------------- permute Wi/bias columns: dst[:, j*4+g] = src[:, g*256+j] ----------------
__global__ void permute_kernel(const float* __restrict__ W, const float* __restrict__ b,
                               float* __restrict__ Wp, float* __restrict__ bp, int K) {
    int idx = blockIdx.x * blockDim.x + threadIdx.x;    // over K*1024
    if (idx >= K * 1024) return;
    int colp = idx & 1023, k = idx >> 10;
    int j = colp >> 2, g = colp & 3;
    Wp[idx] = __ldg(&W[(size_t)k * 1024 + g * 256 + j]);
    if (idx < 1024) bp[idx] = __ldg(&b[g * 256 + j]);
}

// ---------------- embedding gather -> bf16 ----------------
__global__ void gather_kernel(const int* __restrict__ tok, const float* __restrict__ emb) {
    size_t idx = (size_t)blockIdx.x * blockDim.x + threadIdx.x;  // over 2M chunks of 8
    int row = (int)(idx >> 5);
    int f   = (int)(idx & 31);
    int t   = __ldg(&tok[row]);
    const float4* src = (const float4*)(emb + (size_t)t * 256 + f * 8);
    float4 a = __ldg(src);
    float4 b = __ldg(src + 1);
    uint4 o;
    __nv_bfloat162 p0 = __floats2bfloat162_rn(a.x, a.y);
    __nv_bfloat162 p1 = __floats2bfloat162_rn(a.z, a.w);
    __nv_bfloat162 p2 = __floats2bfloat162_rn(b.x, b.y);
    __nv_bfloat162 p3 = __floats2bfloat162_rn(b.z, b.w);
    o.x = *reinterpret_cast<unsigned*>(&p0);
    o.y = *reinterpret_cast<unsigned*>(&p1);
    o.z = *reinterpret_cast<unsigned*>(&p2);
    o.w = *reinterpret_cast<unsigned*>(&p3);
    ((uint4*)g_x)[idx] = o;
}

// ---------------- bf16 GEMM (A bf16): C[M,N] = A[M,K] @ B[K,N] ----------------
#define GLDA 40
#define GLDB 136
__global__ __launch_bounds__(256, 2) void gemm_bf16(const __nv_bfloat16* __restrict__ A,
                                                    const float* __restrict__ B,
                                                    float* __restrict__ C,
                                                    int N, int K) {
    __shared__ __nv_bfloat16 As[2][128 * GLDA];
    __shared__ __nv_bfloat16 Bs[2][32 * GLDB];
    const int tid = threadIdx.x;
    const int w   = tid >> 5;
    const int m0  = blockIdx.y * 128;
    const int n0  = blockIdx.x * 128;
    const int wm0 = (w >> 2) * 64;
    const int wn0 = (w & 3) * 32;

    wmma::fragment<wmma::accumulator, 16, 16, 16, float> c[4][2];
    #pragma unroll
    for (int i = 0; i < 4; i++)
        #pragma unroll
        for (int j = 0; j < 2; j++) wmma::fill_fragment(c[i][j], 0.0f);

    uint4  ra[2];
    float4 rb[4];

    #pragma unroll
    for (int p = 0; p < 2; p++) {
        int idx = tid + p * 256;
        int row = idx >> 2, c8 = idx & 3;
        ra[p] = __ldg(&((const uint4*)(A + (size_t)(m0 + row) * K))[c8]);
    }
    #pragma unroll
    for (int p = 0; p < 4; p++) {
        int idx = tid + p * 256;
        int row = idx >> 5, c4 = idx & 31;
        rb[p] = __ldg(&((const float4*)(B + (size_t)row * N + n0))[c4]);
    }
    #pragma unroll
    for (int p = 0; p < 2; p++) {
        int idx = tid + p * 256;
        int row = idx >> 2, c8 = idx & 3;
        *(uint4*)(&As[0][row * GLDA + c8 * 8]) = ra[p];
    }
    #pragma unroll
    for (int p = 0; p < 4; p++) {
        int idx = tid + p * 256;
        int row = idx >> 5, c4 = idx & 31;
        __nv_bfloat162* dst = (__nv_bfloat162*)(&Bs[0][row * GLDB + c4 * 4]);
        dst[0] = __floats2bfloat162_rn(rb[p].x, rb[p].y);
        dst[1] = __floats2bfloat162_rn(rb[p].z, rb[p].w);
    }
    __syncthreads();

    const int nkt = K >> 5;
    for (int kt = 0; kt < nkt; kt++) {
        const int cur = kt & 1;
        const bool more = (kt + 1 < nkt);
        if (more) {
            #pragma unroll
            for (int p = 0; p < 2; p++) {
                int idx = tid + p * 256;
                int row = idx >> 2, c8 = idx & 3;
                ra[p] = __ldg(&((const uint4*)(A + (size_t)(m0 + row) * K + (kt + 1) * 32))[c8]);
            }
            #pragma unroll
            for (int p = 0; p < 4; p++) {
                int idx = tid + p * 256;
                int row = idx >> 5, c4 = idx & 31;
                rb[p] = __ldg(&((const float4*)(B + (size_t)((kt + 1) * 32 + row) * N + n0))[c4]);
            }
        }
        #pragma unroll
        for (int kk = 0; kk < 32; kk += 16) {
            wmma::fragment<wmma::matrix_a, 16, 16, 16, __nv_bfloat16, wmma::row_major> a[4];
            wmma::fragment<wmma::matrix_b, 16, 16, 16, __nv_bfloat16, wmma::row_major> b[2];
            #pragma unroll
            for (int i = 0; i < 4; i++)
                wmma::load_matrix_sync(a[i], &As[cur][(wm0 + i * 16) * GLDA + kk], GLDA);
            #pragma unroll
            for (int j = 0; j < 2; j++)
                wmma::load_matrix_sync(b[j], &Bs[cur][kk * GLDB + wn0 + j * 16], GLDB);
            #pragma unroll
            for (int i = 0; i < 4; i++)
                #pragma unroll
                for (int j = 0; j < 2; j++)
                    wmma::mma_sync(c[i][j], a[i], b[j], c[i][j]);
        }
        if (more) {
            const int nxt = cur ^ 1;
            #pragma unroll
            for (int p = 0; p < 2; p++) {
                int idx = tid + p * 256;
                int row = idx >> 2, c8 = idx & 3;
                *(uint4*)(&As[nxt][row * GLDA + c8 * 8]) = ra[p];
            }
            #pragma unroll
            for (int p = 0; p < 4; p++) {
                int idx = tid + p * 256;
                int row = idx >> 5, c4 = idx & 31;
                __nv_bfloat162* dst = (__nv_bfloat162*)(&Bs[nxt][row * GLDB + c4 * 4]);
                dst[0] = __floats2bfloat162_rn(rb[p].x, rb[p].y);
                dst[1] = __floats2bfloat162_rn(rb[p].z, rb[p].w);
            }
        }
        __syncthreads();
    }
    #pragma unroll
    for (int i = 0; i < 4; i++)
        #pragma unroll
        for (int j = 0; j < 2; j++)
            wmma::store_matrix_sync(C + (size_t)(m0 + wm0 + i * 16) * N + n0 + wn0 + j * 16,
                                    c[i][j], N, wmma::mem_row_major);
}

// ---------------- persistent LSTM scan (counter sync + float4 gate-interleaved xw) ----------------
#define WHS_LD 72
#define HS_LD  264
#define ZB_LD  68
#define WHS_BYTES (256 * WHS_LD * 2)          // 36864
#define HS_OFF    WHS_BYTES
#define HS_BYTES  (16 * HS_LD * 2)            // 8448
#define ZB_OFF    (HS_OFF + HS_BYTES)         // 45312
#define ZB_BYTES  (2 * 16 * ZB_LD * 4)        // 8704 (two K-half planes)
#define SCAN_SMEM (ZB_OFF + ZB_BYTES)         // 54016

__global__ __launch_bounds__(256, 2) void scan_kernel(
    const float* __restrict__ xw_f, const float* __restrict__ xw_b,
    const float* __restrict__ Wh_f, const float* __restrict__ Wh_b,
    const float* __restrict__ bp_f, const float* __restrict__ bp_b,
    __nv_bfloat16* hb_base, unsigned* ctrs,
    __nv_bfloat16* x1out, float* h2out) {
    extern __shared__ char sm[];
    __nv_bfloat16* Whs = (__nv_bfloat16*)sm;
    __nv_bfloat16* hs  = (__nv_bfloat16*)(sm + HS_OFF);
    float*         zb  = (float*)(sm + ZB_OFF);

    const int tid = threadIdx.x;
    const int w   = tid >> 5;
    const int dir = blockIdx.x >> 7;              // scan2 grid=128 -> always 0
    const int sub = blockIdx.x & 127;
    const int bg  = sub >> 4, ng = sub & 15;
    const int r0  = bg * 8, hc0 = ng * 16;

    const float* xw   = dir ? xw_b : xw_f;
    const float* Whg  = dir ? Wh_b : Wh_f;
    const float* bp   = dir ? bp_b : bp_f;
    __nv_bfloat16* hb = hb_base + (size_t)dir * 2 * (B_SZ * 256);
    unsigned* ctr = ctrs + dir * 8 + bg;

    // zero hs once (rows 8..15 stay zero forever -> M padded to 16)
    for (int i = tid; i < 16 * HS_LD; i += 256) hs[i] = __float2bfloat16(0.f);
    // stage Wh slice bf16: Whs[k][c], c = gate*16+j -> global col gate*256+hc0+j
    for (int i = tid; i < 256 * 64; i += 256) {
        int k = i >> 6, cc = i & 63;
        int gt = cc >> 4, j = cc & 15;
        Whs[k * WHS_LD + cc] =
            __float2bfloat16_rn(__ldg(&Whg[(size_t)k * 1024 + gt * 256 + hc0 + j]));
    }

    // h-load role: row lrow (0..7), 8 bf16 (16B) per thread
    const int lrow = tid >> 5;
    const int lcol = (tid & 31) * 8;
    // MMA role: K-half q, local col base n0
    const int q  = w >> 2;
    const int n0 = (w & 3) * 16;
    // gate role (tid < 128): row gr, h-col gj
    const int gr = tid >> 4, gj = tid & 15;
    // gate-interleaved layouts: the 4 gates of hidden-col (hc0+gj) are contiguous
    const int gicol = (hc0 + gj) * 4;
    float4 b4 = make_float4(0.f, 0.f, 0.f, 0.f);
    if (tid < 128) b4 = *(const float4*)(bp + gicol);
    float c_state = 0.0f;
    const float* xwrow = xw + (size_t)(r0 + gr) * T_SEQ * 1024 + gicol;
    __syncthreads();

    // prefetch xw for steps 0 and 1 (2-deep register pipeline; single float4 each)
    float4 xv0 = make_float4(0.f, 0.f, 0.f, 0.f);
    float4 xv1 = make_float4(0.f, 0.f, 0.f, 0.f);
    if (tid < 128) {
        int ta = dir ? (T_SEQ - 1) : 0;
        int tb = dir ? (T_SEQ - 2) : 1;
        xv0 = __ldcs((const float4*)(xwrow + (size_t)ta * 1024));
        xv1 = __ldcs((const float4*)(xwrow + (size_t)tb * 1024));
    }

    // one scan step; consumes xc (xw for step s), refills it with step s+2
    auto do_step = [&](int s, float4& xc) -> bool {
        if (s > 0) {
            // wait for all 16 group CTAs to have published h(s)
            if (tid == 0) {
                const unsigned tgt = 16u * (unsigned)s;
                unsigned v;
                do {
                    asm volatile("ld.acquire.gpu.global.u32 %0, [%1];" : "=r"(v) : "l"(ctr) : "memory");
                } while (v < tgt);
            }
            __syncthreads();
            // load h(s) [8 rows x 256] bf16 from L2 into hs rows 0..7
            {
                const __nv_bfloat16* hread = hb + (s & 1) * (B_SZ * 256) + (r0 + lrow) * 256 + lcol;
                uint4 hv = __ldcg((const uint4*)hread);
                *(uint4*)(hs + lrow * HS_LD + lcol) = hv;
            }
            __syncthreads();
            // K-split MMA: warp (q, n0); 8-deep chain over its 128 k
            {
                wmma::fragment<wmma::accumulator, 16, 16, 16, float> acc;
                wmma::fill_fragment(acc, 0.0f);
                const int kbase = q * 128;
                #pragma unroll
                for (int kt = 0; kt < 8; kt++) {
                    wmma::fragment<wmma::matrix_a, 16, 16, 16, __nv_bfloat16, wmma::row_major> a;
                    wmma::fragment<wmma::matrix_b, 16, 16, 16, __nv_bfloat16, wmma::row_major> b;
                    const int kk = kbase + kt * 16;
                    wmma::load_matrix_sync(a, hs + kk, HS_LD);
                    wmma::load_matrix_sync(b, Whs + kk * WHS_LD + n0, WHS_LD);
                    wmma::mma_sync(acc, a, b, acc);
                }
                wmma::store_matrix_sync(zb + q * (16 * ZB_LD) + n0, acc, ZB_LD, wmma::mem_row_major);
            }
        }
        __syncthreads();

        const bool last = (s == T_SEQ - 1);
        __nv_bfloat16 hv16 = __float2bfloat16(0.f);
        float hval = 0.f;
        if (tid < 128) {
            float zi = b4.x + xc.x, zf = b4.y + xc.y, zg = b4.z + xc.z, zo = b4.w + xc.w;
            if (s > 0) {
                const float* z0 = zb + gr * ZB_LD;
                const float* z1 = z0 + 16 * ZB_LD;
                zi += z0[gj]      + z1[gj];
                zf += z0[16 + gj] + z1[16 + gj];
                zg += z0[32 + gj] + z1[32 + gj];
                zo += z0[48 + gj] + z1[48 + gj];
            }
            c_state = sig_ap(zf) * c_state + sig_ap(zi) * tanh_ap(zg);
            hval = sig_ap(zo) * tanh_ap(c_state);
            hv16 = __float2bfloat16_rn(hval);
            if (!last) {
                // publish h(s+1) — the ONLY store the release has to order
                __stcg((__nv_bfloat16*)(hb + ((s + 1) & 1) * (B_SZ * 256) + (r0 + gr) * 256 + hc0 + gj), hv16);
            }
        }
        const int t_in = dir ? (T_SEQ - 1 - s) : s;
        if (last) {
            if (tid < 128) {
                if (x1out)
                    __stcg(x1out + ((size_t)(r0 + gr) * T_SEQ + t_in) * 512 + dir * 256 + hc0 + gj, hv16);
                if (h2out)
                    h2out[(r0 + gr) * 256 + hc0 + gj] = hval;
            }
            return true;
        }
        __syncthreads();   // all h stores issued before tid0's release
        if (tid == 0)
            asm volatile("red.release.gpu.global.add.u32 [%0], %1;" :: "l"(ctr), "r"(1u) : "memory");
        // post-release: bulk output store + 2-ahead prefetch (off the release path)
        if (tid < 128) {
            if (x1out)
                __stcg(x1out + ((size_t)(r0 + gr) * T_SEQ + t_in) * 512 + dir * 256 + hc0 + gj, hv16);
            if (s + 2 < T_SEQ) {
                int tn = dir ? (T_SEQ - 1 - (s + 2)) : (s + 2);
                xc = __ldcs((const float4*)(xwrow + (size_t)tn * 1024));
            }
        }
        return false;
    };

    for (int s = 0; s < T_SEQ; s += 2) {
        if (do_step(s, xv0)) break;
        if (do_step(s + 1, xv1)) break;
    }
}

// ---------------- head: layer-2 bwd single step + final dot + sigmoid ----------------
__global__ __launch_bounds__(256) void head_kernel(const float* __restrict__ Wi,
                                                   const float* __restrict__ b2,
                                                   const float* __restrict__ Wd,
                                                   const float* __restrict__ bd,
                                                   float* __restrict__ out) {
    __shared__ float xr[512];
    __shared__ float z[1024];
    __shared__ float red[8];
    const int b = blockIdx.x, tid = threadIdx.x;
    const __nv_bfloat16* xrow = g_x1 + ((size_t)b * T_SEQ + (T_SEQ - 1)) * 512;
    xr[tid] = __bfloat162float(xrow[tid]);
    xr[tid + 256] = __bfloat162float(xrow[tid + 256]);
    __syncthreads();
    const int c0 = tid * 4;
    float4 acc = *(const float4*)(b2 + c0);
    for (int k = 0; k < 512; k++) {
        float xv = xr[k];
        float4 wv = __ldg((const float4*)(Wi + (size_t)k * 1024 + c0));
        acc.x = fmaf(xv, wv.x, acc.x);
        acc.y = fmaf(xv, wv.y, acc.y);
        acc.z = fmaf(xv, wv.z, acc.z);
        acc.w = fmaf(xv, wv.w, acc.w);
    }
    *(float4*)(z + c0) = acc;
    __syncthreads();
    float zi = z[tid], zg = z[512 + tid], zo = z[768 + tid];
    float cst = sigf(zi) * tanhf(zg);           // c0 = 0 so forget term vanishes
    float h2b = sigf(zo) * tanhf(cst);
    float pl = g_h2f[b * 256 + tid] * __ldg(&Wd[tid]) + h2b * __ldg(&Wd[256 + tid]);
    #pragma unroll
    for (int off = 16; off; off >>= 1) pl += __shfl_down_sync(0xffffffffu, pl, off);
    if ((tid & 31) == 0) red[tid >> 5] = pl;
    __syncthreads();
    if (tid == 0) {
        float ssum = 0.f;
        #pragma unroll
        for (int q = 0; q < 8; q++) ssum += red[q];
        out[b] = sigf(ssum + bd[0]);
    }
}

// ---------------- launch ----------------
extern "C" void kernel_launch(void* const* d_in, const int* in_sizes, int n_in,
                              void* d_out, int out_size) {
    const int*   tokens = (const int*)  d_in[0];
    const float* embed  = (const float*)d_in[1];
    const float* fw1_Wi = (const float*)d_in[2];
    const float* fw1_Wh = (const float*)d_in[3];
    const float* fw1_b  = (const float*)d_in[4];
    const float* bw1_Wi = (const float*)d_in[5];
    const float* bw1_Wh = (const float*)d_in[6];
    const float* bw1_b  = (const float*)d_in[7];
    const float* fw2_Wi = (const float*)d_in[8];
    const float* fw2_Wh = (const float*)d_in[9];
    const float* fw2_b  = (const float*)d_in[10];
    const float* bw2_Wi = (const float*)d_in[11];
    const float* bw2_b  = (const float*)d_in[13];
    const float* Wd     = (const float*)d_in[14];
    const float* bd     = (const float*)d_in[15];
    float* out = (float*)d_out;

    float *pxw1f, *pxw1b, *pxw2, *ph2f, *pw1f, *pw1b, *pw2, *pbp;
    __nv_bfloat16 *px, *px1, *phb;
    unsigned* pctrs;
    cudaGetSymbolAddress((void**)&px,    g_x);
    cudaGetSymbolAddress((void**)&pxw1f, g_xw1f);
    cudaGetSymbolAddress((void**)&pxw1b, g_xw1b);
    cudaGetSymbolAddress((void**)&pxw2,  g_xw2);
    cudaGetSymbolAddress((void**)&px1,   g_x1);
    cudaGetSymbolAddress((void**)&ph2f,  g_h2f);
    cudaGetSymbolAddress((void**)&phb,   g_hb);
    cudaGetSymbolAddress((void**)&pctrs, g_ctrs);
    cudaGetSymbolAddress((void**)&pw1f,  g_wip1f);
    cudaGetSymbolAddress((void**)&pw1b,  g_wip1b);
    cudaGetSymbolAddress((void**)&pw2,   g_wip2);
    cudaGetSymbolAddress((void**)&pbp,   g_bp);

    cudaFuncSetAttribute(scan_kernel, cudaFuncAttributeMaxDynamicSharedMemorySize, SCAN_SMEM);

    init_kernel<<<1, 32>>>();
    gather_kernel<<<8192, 256>>>(tokens, embed);
    permute_kernel<<<1024, 256>>>(fw1_Wi, fw1_b, pw1f, pbp,        256);
    permute_kernel<<<1024, 256>>>(bw1_Wi, bw1_b, pw1b, pbp + 1024, 256);
    permute_kernel<<<2048, 256>>>(fw2_Wi, fw2_b, pw2,  pbp + 2048, 512);
    gemm_bf16<<<dim3(8, 512), 256>>>(px, pw1f, pxw1f, 1024, 256);
    gemm_bf16<<<dim3(8, 512), 256>>>(px, pw1b, pxw1b, 1024, 256);
    scan_kernel<<<256, 256, SCAN_SMEM>>>(pxw1f, pxw1b, fw1_Wh, bw1_Wh, pbp, pbp + 1024,
                                         phb, pctrs, px1, nullptr);
    gemm_bf16<<<dim3(8, 512), 256>>>(px1, pw2, pxw2, 1024, 512);
    scan_kernel<<<128, 256, SCAN_SMEM>>>(pxw2, pxw2, fw2_Wh, fw2_Wh, pbp + 2048, pbp + 2048,
                                         phb + (size_t)2 * 2 * (B_SZ * 256), pctrs + 16,
                                         nullptr, ph2f);
    head_kernel<<<64, 256>>>(bw2_Wi, bw2_b, Wd, bd, out);
}